// round 14
// baseline (speedup 1.0000x reference)
#include <cuda_runtime.h>

typedef unsigned long long u64;

// ---------------- packed f32x2 helpers (Blackwell FFMA2) ----------------
__device__ __forceinline__ u64 pack2(float a, float b) {
    u64 r; asm("mov.b64 %0, {%1, %2};" : "=l"(r) : "f"(a), "f"(b)); return r;
}
__device__ __forceinline__ u64 pack1(float a) { return pack2(a, a); }
__device__ __forceinline__ void unpack2(u64 v, float& a, float& b) {
    asm("mov.b64 {%0, %1}, %2;" : "=f"(a), "=f"(b) : "l"(v));
}
__device__ __forceinline__ u64 fma2(u64 a, u64 b, u64 c) {
    u64 d; asm("fma.rn.f32x2 %0, %1, %2, %3;" : "=l"(d) : "l"(a), "l"(b), "l"(c));
    return d;
}
__device__ __forceinline__ u64 relu2(u64 v) {
    float a, b; unpack2(v, a, b);
    a = fmaxf(a, 0.0f); b = fmaxf(b, 0.0f);
    return pack2(a, b);
}

// ---------------- constants ----------------
#define NTHREADS 128
#define ROWS_PER_THREAD 2
static constexpr int BATCH = 2097152;
static constexpr int CHUNK = BATCH / ROWS_PER_THREAD;  // 1048576

// ---------------- padded weight table (u64 indices), bias embedded -------
// stage1 fused: 5 rows, stride 10: [w0..w7, b, pad]       [0,50)
// W2..W4:       5 rows, stride 6:  [w0..w4, b]            [50,80) [80,110) [110,140)
// W5:           4 rows, stride 6:  [w0..w4, b]            [140,164)
#define OFF_FW   0
#define OFF_W2   50
#define OFF_W3   80
#define OFF_W4   110
#define OFF_W5   140
#define W_TOTAL  164

// compute fused/padded table entry t directly from raw weights
__device__ __forceinline__ float table_entry(
    int t,
    const float* __restrict__ W0, const float* __restrict__ b0,
    const float* __restrict__ W1, const float* __restrict__ b1,
    const float* __restrict__ W2, const float* __restrict__ b2,
    const float* __restrict__ W3, const float* __restrict__ b3,
    const float* __restrict__ W4, const float* __restrict__ b4,
    const float* __restrict__ W5, const float* __restrict__ b5) {
    if (t < 50) {
        int o = t / 10, k = t % 10;
        if (k < 8) {
            // fused W01[o][k] = sum_h W1[o][h] * W0[h][k]
            float s = 0.0f;
#pragma unroll
            for (int h = 0; h < 5; h++) s += W1[o * 5 + h] * W0[h * 8 + k];
            return s;
        } else if (k == 8) {
            // fused b01[o] = b1[o] + sum_h W1[o][h] * b0[h]
            float s = b1[o];
#pragma unroll
            for (int h = 0; h < 5; h++) s += W1[o * 5 + h] * b0[h];
            return s;
        }
        return 0.0f;
    } else if (t < 80) {
        int i = t - OFF_W2, o = i / 6, k = i % 6;
        return (k < 5) ? W2[o * 5 + k] : b2[o];
    } else if (t < 110) {
        int i = t - OFF_W3, o = i / 6, k = i % 6;
        return (k < 5) ? W3[o * 5 + k] : b3[o];
    } else if (t < 140) {
        int i = t - OFF_W4, o = i / 6, k = i % 6;
        return (k < 5) ? W4[o * 5 + k] : b4[o];
    } else {
        int i = t - OFF_W5, o = i / 6, k = i % 6;
        return (k < 5) ? W5[o * 5 + k] : b5[o];
    }
}

// one hidden stage (5 -> relu(5)) on the single pair; 3 LDS.128 per neuron row
__device__ __forceinline__ void hidden_stage(u64 a[5], const u64* sw, int woff) {
    u64 h[5];
#pragma unroll
    for (int o = 0; o < 5; o++) {
        ulonglong2 wa = *reinterpret_cast<const ulonglong2*>(sw + woff + o * 6);
        ulonglong2 wb = *reinterpret_cast<const ulonglong2*>(sw + woff + o * 6 + 2);
        ulonglong2 wc = *reinterpret_cast<const ulonglong2*>(sw + woff + o * 6 + 4);  // (w4, bias)
        u64 acc = wc.y;  // bias
        acc = fma2(a[0], wa.x, acc);
        acc = fma2(a[1], wa.y, acc);
        acc = fma2(a[2], wb.x, acc);
        acc = fma2(a[3], wb.y, acc);
        acc = fma2(a[4], wc.x, acc);
        h[o] = relu2(acc);
    }
#pragma unroll
    for (int o = 0; o < 5; o++) a[o] = h[o];
}

__global__ __launch_bounds__(NTHREADS, 8) void mlp_kernel(
    const float4* __restrict__ x, float4* __restrict__ out,
    const float* __restrict__ W0, const float* __restrict__ b0,
    const float* __restrict__ W1, const float* __restrict__ b1,
    const float* __restrict__ W2, const float* __restrict__ b2,
    const float* __restrict__ W3, const float* __restrict__ b3,
    const float* __restrict__ W4, const float* __restrict__ b4,
    const float* __restrict__ W5, const float* __restrict__ b5) {
    __shared__ __align__(16) u64 sw[W_TOTAL];
    const int t = threadIdx.x;
    const int idx = blockIdx.x * NTHREADS + t;  // 0..CHUNK-1
    const float4* xp = x + 2u * (unsigned)idx;

    // front-batch input loads: row idx and row idx+CHUNK (4 x LDG.128)
    float4 xa0 = __ldg(xp);
    float4 xa1 = __ldg(xp + 1);
    float4 xb0 = __ldg(xp + (size_t)(2 * CHUNK));
    float4 xb1 = __ldg(xp + (size_t)(2 * CHUNK) + 1);

    // in-kernel weight prep: fuse layer0 into layer1, build packed table
    {
        int i0 = t, i1 = t + NTHREADS;
        float v0 = table_entry(i0, W0, b0, W1, b1, W2, b2, W3, b3, W4, b4, W5, b5);
        sw[i0] = pack1(v0);
        if (i1 < W_TOTAL) {
            float v1 = table_entry(i1, W0, b0, W1, b1, W2, b2, W3, b3, W4, b4, W5, b5);
            sw[i1] = pack1(v1);
        }
    }
    __syncthreads();

    // pack inputs (row A lane0, row B lane1)
    u64 xv[8];
    xv[0] = pack2(xa0.x, xb0.x); xv[1] = pack2(xa0.y, xb0.y);
    xv[2] = pack2(xa0.z, xb0.z); xv[3] = pack2(xa0.w, xb0.w);
    xv[4] = pack2(xa1.x, xb1.x); xv[5] = pack2(xa1.y, xb1.y);
    xv[6] = pack2(xa1.z, xb1.z); xv[7] = pack2(xa1.w, xb1.w);

    // ---- stage 1: fused layer01 (8 -> relu(5)) ----
    u64 a[5];
#pragma unroll
    for (int o = 0; o < 5; o++) {
        ulonglong2 wa = *reinterpret_cast<const ulonglong2*>(sw + OFF_FW + o * 10);
        ulonglong2 wb = *reinterpret_cast<const ulonglong2*>(sw + OFF_FW + o * 10 + 2);
        ulonglong2 wc = *reinterpret_cast<const ulonglong2*>(sw + OFF_FW + o * 10 + 4);
        ulonglong2 wd = *reinterpret_cast<const ulonglong2*>(sw + OFF_FW + o * 10 + 6);
        u64 bb = sw[OFF_FW + o * 10 + 8];
        u64 acc = bb;
        acc = fma2(xv[0], wa.x, acc);
        acc = fma2(xv[1], wa.y, acc);
        acc = fma2(xv[2], wb.x, acc);
        acc = fma2(xv[3], wb.y, acc);
        acc = fma2(xv[4], wc.x, acc);
        acc = fma2(xv[5], wc.y, acc);
        acc = fma2(xv[6], wd.x, acc);
        acc = fma2(xv[7], wd.y, acc);
        a[o] = relu2(acc);
    }

    // ---- stages 2..4: hidden layers ----
    hidden_stage(a, sw, OFF_W2);
    hidden_stage(a, sw, OFF_W3);
    hidden_stage(a, sw, OFF_W4);

    // ---- stage 5: output layer (5 -> relu(4)) + streaming store ----
    float lo[4], hi[4];
#pragma unroll
    for (int o = 0; o < 4; o++) {
        ulonglong2 wa = *reinterpret_cast<const ulonglong2*>(sw + OFF_W5 + o * 6);
        ulonglong2 wb = *reinterpret_cast<const ulonglong2*>(sw + OFF_W5 + o * 6 + 2);
        ulonglong2 wc = *reinterpret_cast<const ulonglong2*>(sw + OFF_W5 + o * 6 + 4);  // (w4, bias)
        u64 acc = wc.y;  // bias
        acc = fma2(a[0], wa.x, acc);
        acc = fma2(a[1], wa.y, acc);
        acc = fma2(a[2], wb.x, acc);
        acc = fma2(a[3], wb.y, acc);
        acc = fma2(a[4], wc.x, acc);
        acc = relu2(acc);
        unpack2(acc, lo[o], hi[o]);
    }
    float4* op = out + idx;
    __stcs(op, make_float4(lo[0], lo[1], lo[2], lo[3]));
    __stcs(op + (size_t)CHUNK, make_float4(hi[0], hi[1], hi[2], hi[3]));
}

extern "C" void kernel_launch(void* const* d_in, const int* in_sizes, int n_in,
                              void* d_out, int out_size) {
    const float* x  = (const float*)d_in[0];
    const float* W0 = (const float*)d_in[1];
    const float* b0 = (const float*)d_in[2];
    const float* W1 = (const float*)d_in[3];
    const float* b1 = (const float*)d_in[4];
    const float* W2 = (const float*)d_in[5];
    const float* b2 = (const float*)d_in[6];
    const float* W3 = (const float*)d_in[7];
    const float* b3 = (const float*)d_in[8];
    const float* W4 = (const float*)d_in[9];
    const float* b4 = (const float*)d_in[10];
    const float* W5 = (const float*)d_in[11];
    const float* b5 = (const float*)d_in[12];

    const int grid = (BATCH / ROWS_PER_THREAD) / NTHREADS;  // 8192
    mlp_kernel<<<grid, NTHREADS>>>((const float4*)x, (float4*)d_out,
                                   W0, b0, W1, b1, W2, b2, W3, b3, W4, b4, W5, b5);
}

// round 15
// speedup vs baseline: 1.3159x; 1.3159x over previous
#include <cuda_runtime.h>

typedef unsigned long long u64;

// ---------------- packed f32x2 helpers (Blackwell FFMA2) ----------------
__device__ __forceinline__ u64 pack2(float a, float b) {
    u64 r; asm("mov.b64 %0, {%1, %2};" : "=l"(r) : "f"(a), "f"(b)); return r;
}
__device__ __forceinline__ u64 pack1(float a) { return pack2(a, a); }
__device__ __forceinline__ void unpack2(u64 v, float& a, float& b) {
    asm("mov.b64 {%0, %1}, %2;" : "=f"(a), "=f"(b) : "l"(v));
}
__device__ __forceinline__ u64 fma2(u64 a, u64 b, u64 c) {
    u64 d; asm("fma.rn.f32x2 %0, %1, %2, %3;" : "=l"(d) : "l"(a), "l"(b), "l"(c));
    return d;
}
__device__ __forceinline__ u64 relu2(u64 v) {
    float a, b; unpack2(v, a, b);
    a = fmaxf(a, 0.0f); b = fmaxf(b, 0.0f);
    return pack2(a, b);
}

// ---------------- constants ----------------
#define NTHREADS 128
#define ROWS_PER_THREAD 4
#define PAIRS 2
#define NBLOCKS 1184           // 148 SMs x 8 blocks: exactly one residency wave
#define NTILES 4096            // total work tiles (each = 128 threads x 4 rows)
static constexpr int BATCH = 2097152;
static constexpr int CHUNK = BATCH / ROWS_PER_THREAD;  // 524288

// ---------------- padded weight table (u64 indices), bias embedded -------
// stage1 fused: 5 rows, stride 10: [w0..w7, b, pad]       [0,50)
// W2..W4:       5 rows, stride 6:  [w0..w4, b]            [50,80) [80,110) [110,140)
// W5:           4 rows, stride 6:  [w0..w4, b]            [140,164)
#define OFF_FW   0
#define OFF_W2   50
#define OFF_W3   80
#define OFF_W4   110
#define OFF_W5   140
#define W_TOTAL  164

// compute fused/padded table entry t directly from raw weights
__device__ __forceinline__ float table_entry(
    int t,
    const float* __restrict__ W0, const float* __restrict__ b0,
    const float* __restrict__ W1, const float* __restrict__ b1,
    const float* __restrict__ W2, const float* __restrict__ b2,
    const float* __restrict__ W3, const float* __restrict__ b3,
    const float* __restrict__ W4, const float* __restrict__ b4,
    const float* __restrict__ W5, const float* __restrict__ b5) {
    if (t < 50) {
        int o = t / 10, k = t % 10;
        if (k < 8) {
            // fused W01[o][k] = sum_h W1[o][h] * W0[h][k]
            float s = 0.0f;
#pragma unroll
            for (int h = 0; h < 5; h++) s += W1[o * 5 + h] * W0[h * 8 + k];
            return s;
        } else if (k == 8) {
            // fused b01[o] = b1[o] + sum_h W1[o][h] * b0[h]
            float s = b1[o];
#pragma unroll
            for (int h = 0; h < 5; h++) s += W1[o * 5 + h] * b0[h];
            return s;
        }
        return 0.0f;
    } else if (t < 80) {
        int i = t - OFF_W2, o = i / 6, k = i % 6;
        return (k < 5) ? W2[o * 5 + k] : b2[o];
    } else if (t < 110) {
        int i = t - OFF_W3, o = i / 6, k = i % 6;
        return (k < 5) ? W3[o * 5 + k] : b3[o];
    } else if (t < 140) {
        int i = t - OFF_W4, o = i / 6, k = i % 6;
        return (k < 5) ? W4[o * 5 + k] : b4[o];
    } else {
        int i = t - OFF_W5, o = i / 6, k = i % 6;
        return (k < 5) ? W5[o * 5 + k] : b5[o];
    }
}

// one hidden stage (5 -> relu(5)): 3x LDS.128 per neuron row (weights+bias),
// each row applied to both pairs
__device__ __forceinline__ void hidden_stage(u64 a[PAIRS][5], const u64* sw, int woff) {
    u64 h[PAIRS][5];
#pragma unroll
    for (int o = 0; o < 5; o++) {
        ulonglong2 wa = *reinterpret_cast<const ulonglong2*>(sw + woff + o * 6);
        ulonglong2 wb = *reinterpret_cast<const ulonglong2*>(sw + woff + o * 6 + 2);
        ulonglong2 wc = *reinterpret_cast<const ulonglong2*>(sw + woff + o * 6 + 4);  // (w4, bias)
#pragma unroll
        for (int p = 0; p < PAIRS; p++) {
            u64 acc = wc.y;  // bias
            acc = fma2(a[p][0], wa.x, acc);
            acc = fma2(a[p][1], wa.y, acc);
            acc = fma2(a[p][2], wb.x, acc);
            acc = fma2(a[p][3], wb.y, acc);
            acc = fma2(a[p][4], wc.x, acc);
            h[p][o] = relu2(acc);
        }
    }
#pragma unroll
    for (int p = 0; p < PAIRS; p++)
#pragma unroll
        for (int o = 0; o < 5; o++) a[p][o] = h[p][o];
}

__global__ __launch_bounds__(NTHREADS, 8) void mlp_kernel(
    const float4* __restrict__ x, float4* __restrict__ out,
    const float* __restrict__ W0, const float* __restrict__ b0,
    const float* __restrict__ W1, const float* __restrict__ b1,
    const float* __restrict__ W2, const float* __restrict__ b2,
    const float* __restrict__ W3, const float* __restrict__ b3,
    const float* __restrict__ W4, const float* __restrict__ b4,
    const float* __restrict__ W5, const float* __restrict__ b5) {
    __shared__ __align__(16) u64 sw[W_TOTAL];
    const int t = threadIdx.x;

    // weight table built ONCE per block (persistent grid-stride amortization)
    {
        int i0 = t, i1 = t + NTHREADS;
        float v0 = table_entry(i0, W0, b0, W1, b1, W2, b2, W3, b3, W4, b4, W5, b5);
        sw[i0] = pack1(v0);
        if (i1 < W_TOTAL) {
            float v1 = table_entry(i1, W0, b0, W1, b1, W2, b2, W3, b3, W4, b4, W5, b5);
            sw[i1] = pack1(v1);
        }
    }
    __syncthreads();

    // grid-stride over work tiles; body identical to the R4 champion
    for (int tile = blockIdx.x; tile < NTILES; tile += NBLOCKS) {
        const int idx = tile * NTHREADS + t;  // 0..CHUNK-1
        const float4* xp = x + 2u * (unsigned)idx;

        // front-batch input loads (8 x LDG.128)
        float4 xr0[ROWS_PER_THREAD], xr1[ROWS_PER_THREAD];
#pragma unroll
        for (int r = 0; r < ROWS_PER_THREAD; r++) {
            const float4* xr = xp + (size_t)r * (2 * CHUNK);
            xr0[r] = __ldg(xr);
            xr1[r] = __ldg(xr + 1);
        }

        // ---- stage 1: fused layer01 (8 -> relu(5)) ----
        u64 a[PAIRS][5];
#pragma unroll
        for (int o = 0; o < 5; o++) {
            ulonglong2 wa = *reinterpret_cast<const ulonglong2*>(sw + OFF_FW + o * 10);
            ulonglong2 wb = *reinterpret_cast<const ulonglong2*>(sw + OFF_FW + o * 10 + 2);
            ulonglong2 wc = *reinterpret_cast<const ulonglong2*>(sw + OFF_FW + o * 10 + 4);
            ulonglong2 wd = *reinterpret_cast<const ulonglong2*>(sw + OFF_FW + o * 10 + 6);
            u64 bb = sw[OFF_FW + o * 10 + 8];
#pragma unroll
            for (int p = 0; p < PAIRS; p++) {
                const int ra = 2 * p, rb = 2 * p + 1;
                u64 acc = bb;  // bias
                acc = fma2(pack2(xr0[ra].x, xr0[rb].x), wa.x, acc);
                acc = fma2(pack2(xr0[ra].y, xr0[rb].y), wa.y, acc);
                acc = fma2(pack2(xr0[ra].z, xr0[rb].z), wb.x, acc);
                acc = fma2(pack2(xr0[ra].w, xr0[rb].w), wb.y, acc);
                acc = fma2(pack2(xr1[ra].x, xr1[rb].x), wc.x, acc);
                acc = fma2(pack2(xr1[ra].y, xr1[rb].y), wc.y, acc);
                acc = fma2(pack2(xr1[ra].z, xr1[rb].z), wd.x, acc);
                acc = fma2(pack2(xr1[ra].w, xr1[rb].w), wd.y, acc);
                a[p][o] = relu2(acc);
            }
        }

        // ---- stages 2..4: hidden layers ----
        hidden_stage(a, sw, OFF_W2);
        hidden_stage(a, sw, OFF_W3);
        hidden_stage(a, sw, OFF_W4);

        // ---- stage 5: output layer (5 -> relu(4)) + streaming store ----
        float res[ROWS_PER_THREAD][4];
#pragma unroll
        for (int o = 0; o < 4; o++) {
            ulonglong2 wa = *reinterpret_cast<const ulonglong2*>(sw + OFF_W5 + o * 6);
            ulonglong2 wb = *reinterpret_cast<const ulonglong2*>(sw + OFF_W5 + o * 6 + 2);
            ulonglong2 wc = *reinterpret_cast<const ulonglong2*>(sw + OFF_W5 + o * 6 + 4);
#pragma unroll
            for (int p = 0; p < PAIRS; p++) {
                u64 acc = wc.y;  // bias
                acc = fma2(a[p][0], wa.x, acc);
                acc = fma2(a[p][1], wa.y, acc);
                acc = fma2(a[p][2], wb.x, acc);
                acc = fma2(a[p][3], wb.y, acc);
                acc = fma2(a[p][4], wc.x, acc);
                acc = relu2(acc);
                unpack2(acc, res[2 * p][o], res[2 * p + 1][o]);
            }
        }
        float4* op = out + idx;
#pragma unroll
        for (int r = 0; r < ROWS_PER_THREAD; r++) {
            __stcs(op + (size_t)r * CHUNK,
                   make_float4(res[r][0], res[r][1], res[r][2], res[r][3]));
        }
    }
}

extern "C" void kernel_launch(void* const* d_in, const int* in_sizes, int n_in,
                              void* d_out, int out_size) {
    const float* x  = (const float*)d_in[0];
    const float* W0 = (const float*)d_in[1];
    const float* b0 = (const float*)d_in[2];
    const float* W1 = (const float*)d_in[3];
    const float* b1 = (const float*)d_in[4];
    const float* W2 = (const float*)d_in[5];
    const float* b2 = (const float*)d_in[6];
    const float* W3 = (const float*)d_in[7];
    const float* b3 = (const float*)d_in[8];
    const float* W4 = (const float*)d_in[9];
    const float* b4 = (const float*)d_in[10];
    const float* W5 = (const float*)d_in[11];
    const float* b5 = (const float*)d_in[12];

    mlp_kernel<<<NBLOCKS, NTHREADS>>>((const float4*)x, (float4*)d_out,
                                      W0, b0, W1, b1, W2, b2, W3, b3, W4, b4, W5, b5);
}